// round 5
// baseline (speedup 1.0000x reference)
#include <cuda_runtime.h>
#include <cstdint>

typedef unsigned long long u64;

// Problem constants
#define BB   8
#define NN   8192
#define MM   2000
#define KK   16
#define C1W  128
#define C2W  256
#define NOUT 100

#define G1   8          // grid for raw points  (cell 1/8)
#define G2   5          // grid for sub points  (cell 1/5)

// ---------------- scratch (device globals; no allocations allowed) ----------
__device__ float  g_sub [BB * MM * 3];
__device__ int    g_idx1[BB * MM * KK];
__device__ int    g_idx2[BB * MM * KK];
__device__ float  g_f1  [BB * MM * C1W];
__device__ float  g_f2  [BB * MM * C2W];
__device__ float4 g_W2q [33 * C2W];

// grid structures
__device__ float4 g_pts1 [BB * NN];          // (x,y,z,|p|^2) cell-sorted
__device__ int    g_pidx1[BB * NN];          // original index
__device__ int    g_strt1[BB * (G1*G1*G1 + 1)];
__device__ float4 g_pts2 [BB * MM];
__device__ int    g_pidx2[BB * MM];
__device__ int    g_strt2[BB * (G2*G2*G2 + 1)];

__device__ __forceinline__ u64 ffma2(u64 a, u64 b, u64 c) {
    u64 d;
    asm("fma.rn.f32x2 %0, %1, %2, %3;" : "=l"(d) : "l"(a), "l"(b), "l"(c));
    return d;
}
__device__ __forceinline__ unsigned redux_max_u32(unsigned v) {
    unsigned r;
    asm("redux.sync.max.u32 %0, %1, 0xffffffff;" : "=r"(r) : "r"(v));
    return r;
}
__device__ __forceinline__ unsigned redux_min_u32(unsigned v) {
    unsigned r;
    asm("redux.sync.min.u32 %0, %1, 0xffffffff;" : "=r"(r) : "r"(v));
    return r;
}
__device__ __forceinline__ u64 pack2(float lo, float hi) {
    return ((u64)__float_as_uint(hi) << 32) | __float_as_uint(lo);
}

// ---------------- W2 prep ----------------------------------------------------
__global__ void w2prep_kernel(const float* __restrict__ W2) {
    int t = blockIdx.x * 256 + threadIdx.x;
    if (t >= 33 * C2W) return;
    int fq = t >> 8, c = t & 255;
    float v[4];
#pragma unroll
    for (int e = 0; e < 4; e++) {
        int fp = fq * 4 + e;
        float val = 0.f;
        if (fp < 131) {
            int r = (fp < 128) ? (fp + 3) : (fp - 128);
            val = W2[r * C2W + c];
        }
        v[e] = val;
    }
    g_W2q[t] = make_float4(v[0], v[1], v[2], v[3]);
}

// ---------------- FPS (unchanged math) --------------------------------------
__global__ void __launch_bounds__(1024, 1) fps_kernel(const float* __restrict__ x) {
    const int b = blockIdx.x;
    const float* xb = x + (size_t)b * NN * 3;
    const int t = threadIdx.x;
    const int lane = t & 31, warp = t >> 5;

    float px[8], py[8], pz[8], mind[8];
#pragma unroll
    for (int j = 0; j < 8; j++) {
        int i = t + j * 1024;
        px[j] = xb[3 * i]; py[j] = xb[3 * i + 1]; pz[j] = xb[3 * i + 2];
        mind[j] = 1e30f;
    }

    __shared__ unsigned s_val[2][32];
    __shared__ unsigned s_idx[2][32];

    if (t == 0) {
        float* sp = g_sub + (size_t)(b * MM) * 3;
        sp[0] = xb[0]; sp[1] = xb[1]; sp[2] = xb[2];
    }
    float cx = xb[0], cy = xb[1], cz = xb[2];

    for (int step = 1; step < MM; step++) {
        float bv = -1.0f; unsigned bidx = 0;
#pragma unroll
        for (int j = 0; j < 8; j++) {
            float dx = px[j] - cx, dy = py[j] - cy, dz = pz[j] - cz;
            float d = dx * dx + dy * dy + dz * dz;
            float mj = fminf(mind[j], d);
            mind[j] = mj;
            if (mj > bv) { bv = mj; bidx = (unsigned)(t + j * 1024); }
        }
        unsigned vb = __float_as_uint(bv);
        unsigned wmax = redux_max_u32(vb);
        unsigned widx = redux_min_u32(vb == wmax ? bidx : 0xffffffffu);
        int buf = step & 1;
        if (lane == 0) { s_val[buf][warp] = wmax; s_idx[buf][warp] = widx; }
        __syncthreads();
        unsigned v2 = s_val[buf][lane];
        unsigned i2 = s_idx[buf][lane];
        unsigned bmax = redux_max_u32(v2);
        unsigned bix = redux_min_u32(v2 == bmax ? i2 : 0xffffffffu);

        cx = xb[3 * bix]; cy = xb[3 * bix + 1]; cz = xb[3 * bix + 2];
        if (t == 0) {
            float* sp = g_sub + (size_t)(b * MM + step) * 3;
            sp[0] = cx; sp[1] = cy; sp[2] = cz;
        }
    }
}

// ---------------- grid build: one block per batch ---------------------------
__global__ void __launch_bounds__(512) build_grid_kernel(
    const float* __restrict__ src, int n, int G,
    float4* __restrict__ pts, int* __restrict__ pidx, int* __restrict__ cellstart)
{
    const int b = blockIdx.x;
    const int tid = threadIdx.x;
    const int G3 = G * G * G;
    const float fG = (float)G;
    const float* sp = (src ? src : (const float*)g_sub) + (size_t)b * n * 3;

    __shared__ int hist[512];
    __shared__ int cur[512];
    __shared__ int wsum[16];
    __shared__ short s_cid[8192];

    if (tid < G3) hist[tid] = 0;
    __syncthreads();

    for (int i = tid; i < n; i += 512) {
        const float* p = sp + 3 * i;
        int cx = min(G - 1, max(0, (int)(p[0] * fG)));
        int cy = min(G - 1, max(0, (int)(p[1] * fG)));
        int cz = min(G - 1, max(0, (int)(p[2] * fG)));
        int cid = (cz * G + cy) * G + cx;
        s_cid[i] = (short)cid;
        atomicAdd(&hist[cid], 1);
    }
    __syncthreads();

    // exclusive scan over G3 counters
    int lane = tid & 31, wid = tid >> 5;
    int cnt = (tid < G3) ? hist[tid] : 0;
    int v = cnt;
#pragma unroll
    for (int o = 1; o < 32; o <<= 1) {
        int t2 = __shfl_up_sync(0xffffffffu, v, o);
        if (lane >= o) v += t2;
    }
    if (lane == 31) wsum[wid] = v;
    __syncthreads();
    if (tid == 0) {
        int acc = 0;
        for (int w = 0; w < 16; w++) { int t2 = wsum[w]; wsum[w] = acc; acc += t2; }
    }
    __syncthreads();
    int excl = v - cnt + wsum[wid];
    if (tid < G3) { cellstart[b * (G3 + 1) + tid] = excl; cur[tid] = excl; }
    if (tid == 0) cellstart[b * (G3 + 1) + G3] = n;
    __syncthreads();

    for (int i = tid; i < n; i += 512) {
        int cid = s_cid[i];
        int pos = atomicAdd(&cur[cid], 1);
        const float* p = sp + 3 * i;
        float x0 = p[0], y0 = p[1], z0 = p[2];
        pts[(size_t)b * n + pos] = make_float4(x0, y0, z0, x0 * x0 + y0 * y0 + z0 * z0);
        pidx[(size_t)b * n + pos] = i;
    }
}

// ---------------- grid KNN: ring search, 8-way split, exact ------------------
template<int G, int NSRC>
__global__ void __launch_bounds__(256) knn_grid_kernel(
    const float4* __restrict__ pts, const int* __restrict__ pidx,
    const int* __restrict__ cellstart, int* __restrict__ outidx)
{
    constexpr int G3 = G * G * G;
    __shared__ float md[16 * 256];
    __shared__ int   mi[16 * 256];
    __shared__ int   s_done[32];

    const int tid = threadIdx.x;
    const int s = tid & 7;
    const int b = blockIdx.y;
    const int j = blockIdx.x * 32 + (tid >> 3);        // gridded query slot
    const bool qvalid = (j < MM);
    const float fG = (float)G;

    float qx = 0, qy = 0, qz = 0, qq = 0;
    int cqx = 0, cqy = 0, cqz = 0;
    if (qvalid) {
        float4 qp = g_pts2[(size_t)b * MM + j];
        qx = qp.x; qy = qp.y; qz = qp.z; qq = qp.w;
        cqx = min(G - 1, max(0, (int)(qx * fG)));
        cqy = min(G - 1, max(0, (int)(qy * fG)));
        cqz = min(G - 1, max(0, (int)(qz * fG)));
    }

    float dist[KK]; int idxr[KK];
#pragma unroll
    for (int r = 0; r < KK; r++) { dist[r] = 1e38f; idxr[r] = 0x7fffffff; }

    if (tid < 32) s_done[tid] = (blockIdx.x * 32 + tid >= MM) ? 1 : 0;
    __syncthreads();
    int qd = qvalid ? 0 : 1;

    const int* cs = cellstart + b * (G3 + 1);

    for (int R = 1; R <= G; R++) {
        if (!qd) {
            int zlo = max(cqz - R, 0), zhi = min(cqz + R, G - 1);
            int ylo = max(cqy - R, 0), yhi = min(cqy + R, G - 1);
            int xlo = max(cqx - R, 0), xhi = min(cqx + R, G - 1);
            int c = 0;
            for (int cz = zlo; cz <= zhi; cz++)
                for (int cy = ylo; cy <= yhi; cy++)
                    for (int cx = xlo; cx <= xhi; cx++) {
                        if (R > 1) {
                            int ch = max(abs(cx - cqx), max(abs(cy - cqy), abs(cz - cqz)));
                            if (ch < R) continue;     // scanned in earlier ring
                        }
                        if (((c++) & 7) != s) continue;
                        int cid = (cz * G + cy) * G + cx;
                        int beg = cs[cid], end = cs[cid + 1];
                        for (int i = beg; i < end; i++) {
                            float4 p = pts[(size_t)b * NSRC + i];
                            int id = pidx[(size_t)b * NSRC + i];
                            float t2 = qx * p.x;
                            t2 = fmaf(qy, p.y, t2);
                            t2 = fmaf(qz, p.z, t2);
                            float d = fmaf(-2.f, t2, qq + p.w);
                            if (d < dist[KK - 1] ||
                                (d == dist[KK - 1] && id < idxr[KK - 1])) {
                                dist[KK - 1] = d; idxr[KK - 1] = id;
#pragma unroll
                                for (int r = KK - 1; r > 0; --r) {
                                    bool sw = (dist[r] < dist[r - 1]) ||
                                              (dist[r] == dist[r - 1] && idxr[r] < idxr[r - 1]);
                                    if (sw) {
                                        float td = dist[r]; dist[r] = dist[r - 1]; dist[r - 1] = td;
                                        int ti = idxr[r]; idxr[r] = idxr[r - 1]; idxr[r - 1] = ti;
                                    }
                                }
                            }
                        }
                    }
        }
        __syncthreads();
        if (!qd) {
#pragma unroll
            for (int r = 0; r < KK; r++) {
                md[r * 256 + tid] = dist[r];
                mi[r * 256 + tid] = idxr[r];
            }
        }
        __syncthreads();
        if (tid < 32 && !s_done[tid]) {
            int p[8] = {0, 0, 0, 0, 0, 0, 0, 0};
            int picks[KK];
            float d16 = 1e38f;
#pragma unroll 1
            for (int r = 0; r < KK; r++) {
                float bd = 3e38f; int bi = 0x7fffffff; int bs = 0;
#pragma unroll
                for (int ss = 0; ss < 8; ss++) {
                    int ps = p[ss];
                    if (ps < KK) {
                        float d = md[ps * 256 + tid * 8 + ss];
                        int   ii = mi[ps * 256 + tid * 8 + ss];
                        if (d < bd || (d == bd && ii < bi)) { bd = d; bi = ii; bs = ss; }
                    }
                }
                p[bs]++;
                picks[r] = bi;
                d16 = bd;
            }
            float bnd = R * (1.0f / G);
            bnd = bnd * bnd * 0.9999f;
            if (d16 <= bnd || R >= G) {
                int q = g_pidx2[(size_t)b * MM + blockIdx.x * 32 + tid];  // original query idx
                int* op = outidx + (size_t)(b * MM + q) * KK;
#pragma unroll
                for (int r = 0; r < KK; r++) op[r] = picks[r];
                s_done[tid] = 1;
            }
        }
        __syncthreads();
        qd = s_done[tid >> 3];
        if (__syncthreads_count(qd) == 256) break;
    }
}

// ---------------- Layer 1 ----------------------------------------------------
__global__ void __launch_bounds__(128) layer1_kernel(const float* __restrict__ x,
                                                     const float* __restrict__ W1,
                                                     const float* __restrict__ b1) {
    __shared__ float sW[6 * C1W];
    int tid = threadIdx.x;
    for (int i = tid; i < 6 * C1W; i += 128) sW[i] = W1[i];
    __syncthreads();

    int warp = tid >> 5, lane = tid & 31;
    int b = blockIdx.y;
    int m = blockIdx.x * 4 + warp;

    const float* cp = g_sub + (size_t)(b * MM + m) * 3;
    float cx = cp[0], cy = cp[1], cz = cp[2];
    int c0 = lane * 4;
    float bb[4] = { b1[c0], b1[c0 + 1], b1[c0 + 2], b1[c0 + 3] };
    float best[4] = { 0.f, 0.f, 0.f, 0.f };
    const int* ip = g_idx1 + (size_t)(b * MM + m) * KK;

#pragma unroll 1
    for (int k = 0; k < KK; k++) {
        int n = ip[k];
        const float* np = x + ((size_t)b * NN + n) * 3;
        float nx = np[0], ny = np[1], nz = np[2];
        float f[6]; f[0] = nx - cx; f[1] = ny - cy; f[2] = nz - cz; f[3] = nx; f[4] = ny; f[5] = nz;
        float a[4] = { bb[0], bb[1], bb[2], bb[3] };
#pragma unroll
        for (int ff = 0; ff < 6; ff++) {
            const float* w = sW + ff * C1W + c0;
            a[0] += f[ff] * w[0]; a[1] += f[ff] * w[1];
            a[2] += f[ff] * w[2]; a[3] += f[ff] * w[3];
        }
#pragma unroll
        for (int e = 0; e < 4; e++) best[e] = fmaxf(best[e], fmaxf(a[e], 0.f));
    }
    *(float4*)(g_f1 + ((size_t)(b * MM + m) * C1W + c0)) =
        make_float4(best[0], best[1], best[2], best[3]);
}

// ---------------- Layer 2: FFMA2 ---------------------------------------------
#define CH 4
__global__ void __launch_bounds__(256, 1) layer2_kernel(const float* __restrict__ b2) {
    __shared__ __align__(16) float sfeat[CH * 16 * 132];
    __shared__ int s_n[CH * 16];

    int b = blockIdx.y, m0 = blockIdx.x * CH;
    int tid = threadIdx.x;

    if (tid < CH * 16) {
        int mm = tid >> 4, k = tid & 15;
        int m = m0 + mm;
        int n = g_idx2[(size_t)(b * MM + m) * KK + k];
        s_n[tid] = n;
        const float* cp = g_sub + (size_t)(b * MM + m) * 3;
        const float* np = g_sub + (size_t)(b * MM + n) * 3;
        float* row = sfeat + tid * 132;
        row[128] = np[0] - cp[0];
        row[129] = np[1] - cp[1];
        row[130] = np[2] - cp[2];
        row[131] = 0.f;
    }
    __syncthreads();
    for (int t = tid; t < CH * 16 * 32; t += 256) {
        int p = t >> 5, fq = t & 31;
        int n = s_n[p];
        float4 v = *(const float4*)(g_f1 + (size_t)(b * MM + n) * C1W + fq * 4);
        *(float4*)(sfeat + p * 132 + fq * 4) = v;
    }
    int c = tid;
    u64 wpk[66];
#pragma unroll
    for (int qd = 0; qd < 33; qd++) {
        float4 w = g_W2q[qd * C2W + c];
        wpk[2 * qd]     = pack2(w.x, w.y);
        wpk[2 * qd + 1] = pack2(w.z, w.w);
    }
    u64 bias = (u64)__float_as_uint(b2[c]);
    __syncthreads();

    float best[CH];
#pragma unroll
    for (int mm = 0; mm < CH; mm++) best[mm] = 0.f;

#pragma unroll 1
    for (int k = 0; k < 16; k++) {
        u64 acc[CH];
#pragma unroll
        for (int mm = 0; mm < CH; mm++) acc[mm] = bias;
#pragma unroll
        for (int q2 = 0; q2 < 33; q2++) {
#pragma unroll
            for (int mm = 0; mm < CH; mm++) {
                const ulonglong2* vrow = (const ulonglong2*)(sfeat + (mm * 16 + k) * 132);
                ulonglong2 v = vrow[q2];
                acc[mm] = ffma2(v.x, wpk[2 * q2], acc[mm]);
                acc[mm] = ffma2(v.y, wpk[2 * q2 + 1], acc[mm]);
            }
        }
#pragma unroll
        for (int mm = 0; mm < CH; mm++) {
            float lo = __uint_as_float((unsigned)(acc[mm] & 0xffffffffu));
            float hi = __uint_as_float((unsigned)(acc[mm] >> 32));
            float a = lo + hi;
            best[mm] = fmaxf(best[mm], fmaxf(a, 0.f));
        }
    }
#pragma unroll
    for (int mm = 0; mm < CH; mm++)
        g_f2[(size_t)(b * MM + m0 + mm) * C2W + c] = best[mm];
}

// ---------------- fused adaptive max+avg pool --------------------------------
__global__ void __launch_bounds__(256) pool_kernel(float* __restrict__ out) {
    int c = threadIdx.x;
    int o = blockIdx.x;
    int b = blockIdx.y;
    const float* f = g_f2 + ((size_t)(b * MM + o * 20) * C2W) + c;
    float mx = -1e38f, sm = 0.f;
#pragma unroll
    for (int w = 0; w < 20; w++) {
        float v = f[(size_t)w * C2W];
        mx = fmaxf(mx, v);
        sm += v;
    }
    out[((size_t)b * C2W + c) * NOUT + o] = mx + sm / 20.0f;
}

// ---------------- launch ------------------------------------------------------
extern "C" void kernel_launch(void* const* d_in, const int* in_sizes, int n_in,
                              void* d_out, int out_size) {
    const float* x  = (const float*)d_in[0];
    const float* W1 = (const float*)d_in[1];
    const float* b1 = (const float*)d_in[2];
    const float* W2 = (const float*)d_in[3];
    const float* b2 = (const float*)d_in[4];
    float* out = (float*)d_out;

    float4* pts1; int* pidx1; int* strt1;
    float4* pts2; int* pidx2; int* strt2;
    int* idx1; int* idx2;
    cudaGetSymbolAddress((void**)&pts1, g_pts1);
    cudaGetSymbolAddress((void**)&pidx1, g_pidx1);
    cudaGetSymbolAddress((void**)&strt1, g_strt1);
    cudaGetSymbolAddress((void**)&pts2, g_pts2);
    cudaGetSymbolAddress((void**)&pidx2, g_pidx2);
    cudaGetSymbolAddress((void**)&strt2, g_strt2);
    cudaGetSymbolAddress((void**)&idx1, g_idx1);   // FIX: device address, not host shadow
    cudaGetSymbolAddress((void**)&idx2, g_idx2);   // FIX: device address, not host shadow

    w2prep_kernel<<<33, 256>>>(W2);
    build_grid_kernel<<<BB, 512>>>(x, NN, G1, pts1, pidx1, strt1);
    fps_kernel<<<BB, 1024>>>(x);
    build_grid_kernel<<<BB, 512>>>(nullptr, MM, G2, pts2, pidx2, strt2);
    knn_grid_kernel<G1, NN><<<dim3((MM + 31) / 32, BB), 256>>>(pts1, pidx1, strt1, idx1);
    knn_grid_kernel<G2, MM><<<dim3((MM + 31) / 32, BB), 256>>>(pts2, pidx2, strt2, idx2);
    layer1_kernel<<<dim3(MM / 4, BB), 128>>>(x, W1, b1);
    layer2_kernel<<<dim3(MM / CH, BB), 256>>>(b2);
    pool_kernel<<<dim3(NOUT, BB), 256>>>(out);
}